// round 12
// baseline (speedup 1.0000x reference)
#include <cuda_runtime.h>
#include <cuda_fp16.h>
#include <cuda_bf16.h>
#include <math.h>
#include <stdint.h>

// Problem constants
#define AA 16
#define BB 16
#define SS 128
#define DD 512
#define NN 256        // A*B
#define LL 5
#define SC 132        // S + L - 1
#define HH 8
#define DK 64

// ---------------- scratch (device globals; no runtime allocation) ----------------
__device__ __half g_xcq[(size_t)NN*SC*DD];     // fp16 concat(q)
__device__ __half g_xck[(size_t)NN*SC*DD];     // fp16 concat(k)
__device__ __half g_yqh[(size_t)NN*SC*DD];     // fp16 projected q
__device__ __half g_ykh[(size_t)NN*SC*DD];     // fp16 projected k
__device__ __half g_qh [(size_t)NN*SS*DD];     // fp16 gathered q
__device__ __half g_kh [(size_t)NN*SS*DD];     // fp16 gathered k
__device__ __half g_vh [(size_t)NN*SS*DD];     // fp16 value (input cvt)
__device__ __half g_vh2[(size_t)NN*SS*DD];     // fp16 projected v
__device__ __half g_xah[(size_t)NN*SS*DD];     // fp16 [S,B,A,D]
__device__ __half g_xf [(size_t)NN*SS*DD];     // fp16 [A,B,S,D]
__device__ __half g_Wh [4*(size_t)DD*DD];      // fp16 Wq,Wk,Wv,Wo

// ---------------- helpers ---------------------------------------------------------
__device__ __forceinline__ unsigned f2tf32(float f) {
    unsigned u;
    asm("cvt.rna.tf32.f32 %0, %1;" : "=r"(u) : "f"(f));
    return u;
}

__device__ __forceinline__ void mma_tf32(float* d, const unsigned* a, const unsigned* b) {
    asm volatile(
        "mma.sync.aligned.m16n8k8.row.col.f32.tf32.tf32.f32 "
        "{%0,%1,%2,%3}, {%4,%5,%6,%7}, {%8,%9}, {%0,%1,%2,%3};"
        : "+f"(d[0]), "+f"(d[1]), "+f"(d[2]), "+f"(d[3])
        : "r"(a[0]), "r"(a[1]), "r"(a[2]), "r"(a[3]),
          "r"(b[0]), "r"(b[1]));
}

__device__ __forceinline__ void mma_f16(float* d, const unsigned* a, const unsigned* b) {
    asm volatile(
        "mma.sync.aligned.m16n8k16.row.col.f32.f16.f16.f32 "
        "{%0,%1,%2,%3}, {%4,%5,%6,%7}, {%8,%9}, {%0,%1,%2,%3};"
        : "+f"(d[0]), "+f"(d[1]), "+f"(d[2]), "+f"(d[3])
        : "r"(a[0]), "r"(a[1]), "r"(a[2]), "r"(a[3]),
          "r"(b[0]), "r"(b[1]));
}

__device__ __forceinline__ void cp16(unsigned* smem_dst, const void* gmem_src) {
    unsigned saddr = (unsigned)__cvta_generic_to_shared(smem_dst);
    asm volatile("cp.async.cg.shared.global [%0], [%1], 16;\n"
                 :: "r"(saddr), "l"(gmem_src));
}

__device__ __forceinline__ unsigned pack_h2(float a, float b) {
    __half2 h = __floats2half2_rn(a, b);
    return *(unsigned*)&h;
}

__device__ __forceinline__ void store2(float* C, size_t idx, float a, float b) {
    *(float2*)&C[idx] = make_float2(a, b);
}
__device__ __forceinline__ void store2(__half* C, size_t idx, float a, float b) {
    *(unsigned*)&C[idx] = pack_h2(a, b);
}

// ---------------- elementwise f32 -> fp16 -----------------------------------------
__global__ void k_cvt_h(const float* __restrict__ src, __half* __restrict__ dst, int n4) {
    int i = blockIdx.x * 256 + threadIdx.x;
    if (i < n4) {
        float4 v = ((const float4*)src)[i];
        ((uint2*)dst)[i] = make_uint2(pack_h2(v.x, v.y), pack_h2(v.z, v.w));
    }
}

// ---------------- concat pad + x -> xc [N,132,D] in fp16 --------------------------
__global__ void k_concat_cvt(const float* __restrict__ x, const float* __restrict__ pad,
                             __half* __restrict__ xc) {
    int idx = blockIdx.x * 256 + threadIdx.x;     // float4 index; total N*SC*128
    int c   = idx & 127;
    int row = idx >> 7;
    int n = row / SC;
    int s = row - n * SC;
    const float4* src;
    if (s < LL - 1)
        src = (const float4*)pad + ((size_t)n*(LL-1) + s)*128 + c;
    else
        src = (const float4*)x   + ((size_t)n*SS + (s - (LL-1)))*128 + c;
    float4 v = *src;
    ((uint2*)xc)[idx] = make_uint2(pack_h2(v.x, v.y), pack_h2(v.z, v.w));
}

// ---------------- fp16 tensor-core GEMM: C[M,512] = A[M,512]@W[512,512]^T + bias --
#define GS 36
#define GSTG (128 * GS)
template<class T>
__global__ void __launch_bounds__(256) gemm_h(const __half* __restrict__ A,
                                              const __half* __restrict__ W,
                                              const float* __restrict__ bias,
                                              T* __restrict__ C) {
    extern __shared__ unsigned sm[];   // [2 stages][As|Bs]
    int tid = threadIdx.x;
    int bm = blockIdx.y * 128;
    int bn = blockIdx.x * 128;
    int wid = tid >> 5, lane = tid & 31;
    int g = lane >> 2, tig = lane & 3;
    int wm = wid & 3, wn = wid >> 2;
    int m0 = wm * 32, n0 = wn * 64;

    const __half* Ab = A + (size_t)bm * 512;
    const __half* Wb = W + (size_t)bn * 512;

    float acc[2][8][4];
#pragma unroll
    for (int mt = 0; mt < 2; mt++)
#pragma unroll
        for (int nt = 0; nt < 8; nt++)
#pragma unroll
            for (int i = 0; i < 4; i++) acc[mt][nt][i] = 0.f;

#define PREFETCH(kt, stg)                                                        \
    {                                                                            \
        unsigned* sA = sm + (stg) * 2 * GSTG;                                    \
        unsigned* sB = sA + GSTG;                                                \
        _Pragma("unroll")                                                        \
        for (int i = 0; i < 4; i++) {                                            \
            int idx = tid + 256 * i;                                             \
            int r = idx >> 3, qd = idx & 7;                                      \
            cp16(sA + r * GS + qd * 4, Ab + (size_t)r * 512 + (kt) + qd * 8);    \
            cp16(sB + r * GS + qd * 4, Wb + (size_t)r * 512 + (kt) + qd * 8);    \
        }                                                                        \
        asm volatile("cp.async.commit_group;\n");                                \
    }

    PREFETCH(0, 0);

#pragma unroll 1
    for (int kt = 0; kt < 512; kt += 64) {
        int stg = (kt >> 6) & 1;
        if (kt + 64 < 512) {
            PREFETCH(kt + 64, stg ^ 1);
            asm volatile("cp.async.wait_group 1;\n");
        } else {
            asm volatile("cp.async.wait_group 0;\n");
        }
        __syncthreads();

        const unsigned* As = sm + stg * 2 * GSTG;
        const unsigned* Bs = As + GSTG;
#pragma unroll
        for (int kc = 0; kc < 4; kc++) {
            int kb2 = kc * 8;                 // word offset within row
            unsigned af[2][4], bf[8][2];
#pragma unroll
            for (int mt = 0; mt < 2; mt++) {
                int row = m0 + mt * 16 + g;
                af[mt][0] = As[row * GS + kb2 + tig];
                af[mt][1] = As[(row + 8) * GS + kb2 + tig];
                af[mt][2] = As[row * GS + kb2 + tig + 4];
                af[mt][3] = As[(row + 8) * GS + kb2 + tig + 4];
            }
#pragma unroll
            for (int nt = 0; nt < 8; nt++) {
                int col = n0 + nt * 8 + g;
                bf[nt][0] = Bs[col * GS + kb2 + tig];
                bf[nt][1] = Bs[col * GS + kb2 + tig + 4];
            }
#pragma unroll
            for (int mt = 0; mt < 2; mt++)
#pragma unroll
                for (int nt = 0; nt < 8; nt++)
                    mma_f16(acc[mt][nt], af[mt], bf[nt]);
        }
        __syncthreads();
    }
#undef PREFETCH

#pragma unroll
    for (int mt = 0; mt < 2; mt++) {
        int row = bm + m0 + mt * 16 + g;
#pragma unroll
        for (int nt = 0; nt < 8; nt++) {
            int col = bn + n0 + nt * 8 + 2 * tig;
            float b0 = bias[col], b1 = bias[col + 1];
            store2(C, (size_t)row * 512 + col, acc[mt][nt][0] + b0, acc[mt][nt][1] + b1);
            store2(C, (size_t)(row + 8) * 512 + col, acc[mt][nt][2] + b0, acc[mt][nt][3] + b1);
        }
    }
}

// ---------------- FUSED local-window weights + scrambled gather -------------------
// One block per n (256 blocks, 256 threads). Stages y[n] (132x512 fp16) in smem,
// computes w[n,s,5] (softmax of center·window dots), then gathers:
//   out[n,s,d] = sum_l w[n,sp,lp] * y[n,sp+lp,d], f=l*S+s, sp=f/5, lp=f%5.
// smem: ys 132 rows x 520 halfs (stride 520 halfs = 260 half2) + ws[128*5] fp32.
#define YS_STR 520
#define WG_SMEM (SC * YS_STR * 2 + SS * LL * 4)   // 137280 + 2560 = 139840 B
__global__ void __launch_bounds__(256) k_wg(const __half* __restrict__ y,
                                            __half* __restrict__ out) {
    extern __shared__ __half ys[];
    float* ws = (float*)(ys + SC * YS_STR);
    int n = blockIdx.x;
    int tid = threadIdx.x;
    int wid = tid >> 5, lane = tid & 31;

    // phase 1: stage y[n] (132*512 halfs = 8448 uint4)
    const uint4* src = (const uint4*)(y + (size_t)n * SC * DD);
    for (int it = tid; it < SC * 64; it += 256) {
        int r = it >> 6, c = it & 63;
        *(uint4*)&ys[r * YS_STR + c * 8] = src[it];
    }
    __syncthreads();

    // phase 2: window scores + softmax -> ws[s*5+l]
    const __half2* ys2 = (const __half2*)ys;
#pragma unroll 1
    for (int si = 0; si < 16; si++) {
        int s = wid * 16 + si;
        const __half2* cen = ys2 + (size_t)(s + LL - 1) * (YS_STR / 2);
        float d0=0.f,d1=0.f,d2=0.f,d3=0.f,d4=0.f;
        for (int i = lane; i < 256; i += 32) {
            float2 cv = __half22float2(cen[i]);
            float2 v0 = __half22float2(ys2[(s+0)*(YS_STR/2) + i]);
            float2 v1 = __half22float2(ys2[(s+1)*(YS_STR/2) + i]);
            float2 v2 = __half22float2(ys2[(s+2)*(YS_STR/2) + i]);
            float2 v3 = __half22float2(ys2[(s+3)*(YS_STR/2) + i]);
            float2 v4 = __half22float2(ys2[(s+4)*(YS_STR/2) + i]);
            d0 += cv.x*v0.x + cv.y*v0.y;
            d1 += cv.x*v1.x + cv.y*v1.y;
            d2 += cv.x*v2.x + cv.y*v2.y;
            d3 += cv.x*v3.x + cv.y*v3.y;
            d4 += cv.x*v4.x + cv.y*v4.y;
        }
#pragma unroll
        for (int off = 16; off; off >>= 1) {
            d0 += __shfl_xor_sync(0xffffffffu, d0, off);
            d1 += __shfl_xor_sync(0xffffffffu, d1, off);
            d2 += __shfl_xor_sync(0xffffffffu, d2, off);
            d3 += __shfl_xor_sync(0xffffffffu, d3, off);
            d4 += __shfl_xor_sync(0xffffffffu, d4, off);
        }
        if (lane == 0) {
            const float sc = 0.044194173824159216f;   // 1/sqrt(512)
            float s0 = d0*sc, s1 = d1*sc, s2 = d2*sc, s3 = d3*sc, s4 = d4*sc;
            float m = fmaxf(fmaxf(fmaxf(s0,s1), fmaxf(s2,s3)), s4);
            float e0 = __expf(s0-m), e1 = __expf(s1-m), e2 = __expf(s2-m),
                  e3 = __expf(s3-m), e4 = __expf(s4-m);
            float inv = 1.f / (e0+e1+e2+e3+e4);
            float* wp = ws + s * LL;
            wp[0]=e0*inv; wp[1]=e1*inv; wp[2]=e2*inv; wp[3]=e3*inv; wp[4]=e4*inv;
        }
    }
    __syncthreads();

    // phase 3: scrambled gather, out[n,s,:] (uint2 = 4 halfs per item)
    uint2* ob = (uint2*)(out + (size_t)n * SS * DD);
#pragma unroll 1
    for (int it = tid; it < SS * 128; it += 256) {
        int s = it >> 7, c = it & 127;
        float4 acc = make_float4(0.f, 0.f, 0.f, 0.f);
#pragma unroll
        for (int l = 0; l < LL; l++) {
            int f  = l * SS + s;
            int sp = f / 5;
            int lp = f - sp * 5;
            float coef = ws[sp * LL + lp];
            uint2 u = *(const uint2*)&ys[(sp + lp) * YS_STR + c * 4];
            float2 f0 = __half22float2(*(__half2*)&u.x);
            float2 f1 = __half22float2(*(__half2*)&u.y);
            acc.x += coef * f0.x; acc.y += coef * f0.y;
            acc.z += coef * f1.x; acc.w += coef * f1.y;
        }
        ob[(size_t)s * 128 + c] = make_uint2(pack_h2(acc.x, acc.y), pack_h2(acc.z, acc.w));
    }
}

// ---------------- attention 1 via fp16 MMA: per (n,h) block, S=128, dk=64 --------
#define A1_QS 36    // word stride Q/K rows (72 halfs)
#define A1_PS 68    // word stride P rows (136 halfs)
#define A1_VS 68    // word stride Vt rows (136 halfs)
__global__ void __launch_bounds__(256) attn1_h(const __half* __restrict__ q,
                                               const __half* __restrict__ k,
                                               const __half* __restrict__ v,
                                               __half* __restrict__ o) {
    extern __shared__ __half hs[];
    __half* Qh = hs;
    __half* Kh = hs + 9216;
    __half* Vt = hs + 18432;
    unsigned* Qw = (unsigned*)Qh;
    unsigned* Kw = (unsigned*)Kh;
    unsigned* Pw = (unsigned*)hs;      // overlay after QK phase
    unsigned* Vw = (unsigned*)Vt;

    int n = blockIdx.x >> 3, h = blockIdx.x & 7;
    int tid = threadIdx.x;
    int lane = tid & 31;
    int g = lane >> 2, tig = lane & 3;
    int m0 = (tid >> 5) * 16;          // warp -> 16 rows

    // stage Q,K: raw fp16 copies (8 halfs/thread/iter)
#pragma unroll
    for (int i = 0; i < 4; i++) {
        int idx = tid + 256 * i;       // 0..1023 = 128 s x 8 dq
        int s = idx >> 3, dq = idx & 7;
        size_t goff = ((size_t)(n * 128 + s)) * 512 + h * 64 + dq * 8;
        *(uint4*)&Qh[s * 72 + dq * 8] = *(const uint4*)(q + goff);
        *(uint4*)&Kh[s * 72 + dq * 8] = *(const uint4*)(k + goff);
    }
    // stage V transposed [d][s] (4 halfs/thread/iter)
#pragma unroll
    for (int i = 0; i < 8; i++) {
        int idx = tid + 256 * i;       // 0..2047 = 128 s x 16 dq
        int s = idx >> 4, dq = idx & 15;
        size_t goff = ((size_t)(n * 128 + s)) * 512 + h * 64 + dq * 4;
        uint2 u = *(const uint2*)(v + goff);
        __half t[4];
        *(uint2*)t = u;
        int d0 = dq * 4;
        Vt[(d0+0) * 136 + s] = t[0];
        Vt[(d0+1) * 136 + s] = t[1];
        Vt[(d0+2) * 136 + s] = t[2];
        Vt[(d0+3) * 136 + s] = t[3];
    }
    __syncthreads();

    float acc[16][4];
#pragma unroll
    for (int nt = 0; nt < 16; nt++)
#pragma unroll
        for (int i = 0; i < 4; i++) acc[nt][i] = 0.f;

#pragma unroll
    for (int kc = 0; kc < 4; kc++) {   // K=64 -> 4 x k16
        int kb2 = kc * 8;
        unsigned af[4];
        af[0] = Qw[(m0 + g) * A1_QS + kb2 + tig];
        af[1] = Qw[(m0 + 8 + g) * A1_QS + kb2 + tig];
        af[2] = Qw[(m0 + g) * A1_QS + kb2 + tig + 4];
        af[3] = Qw[(m0 + 8 + g) * A1_QS + kb2 + tig + 4];
#pragma unroll
        for (int nt = 0; nt < 16; nt++) {
            unsigned bf[2];
            bf[0] = Kw[(nt * 8 + g) * A1_QS + kb2 + tig];
            bf[1] = Kw[(nt * 8 + g) * A1_QS + kb2 + tig + 4];
            mma_f16(acc[nt], af, bf);
        }
    }
    __syncthreads();   // Q/K dead in all warps -> safe to overlay P

    float mx0 = -1e30f, mx1 = -1e30f;
#pragma unroll
    for (int nt = 0; nt < 16; nt++) {
        mx0 = fmaxf(mx0, fmaxf(acc[nt][0], acc[nt][1]));
        mx1 = fmaxf(mx1, fmaxf(acc[nt][2], acc[nt][3]));
    }
    mx0 = fmaxf(mx0, __shfl_xor_sync(0xffffffffu, mx0, 1));
    mx0 = fmaxf(mx0, __shfl_xor_sync(0xffffffffu, mx0, 2));
    mx1 = fmaxf(mx1, __shfl_xor_sync(0xffffffffu, mx1, 1));
    mx1 = fmaxf(mx1, __shfl_xor_sync(0xffffffffu, mx1, 2));
    float sum0 = 0.f, sum1 = 0.f;
#pragma unroll
    for (int nt = 0; nt < 16; nt++) {
        float e0 = __expf(0.125f * (acc[nt][0] - mx0));
        float e1 = __expf(0.125f * (acc[nt][1] - mx0));
        float e2 = __expf(0.125f * (acc[nt][2] - mx1));
        float e3 = __expf(0.125f * (acc[nt][3] - mx1));
        sum0 += e0 + e1;
        sum1 += e2 + e3;
        int cw = nt * 4 + tig;         // word col = (nt*8 + 2tig)/2
        Pw[(m0 + g) * A1_PS + cw]     = pack_h2(e0, e1);
        Pw[(m0 + 8 + g) * A1_PS + cw] = pack_h2(e2, e3);
    }
    sum0 += __shfl_xor_sync(0xffffffffu, sum0, 1);
    sum0 += __shfl_xor_sync(0xffffffffu, sum0, 2);
    sum1 += __shfl_xor_sync(0xffffffffu, sum1, 1);
    sum1 += __shfl_xor_sync(0xffffffffu, sum1, 2);
    float inv0 = 1.f / sum0, inv1 = 1.f / sum1;
    __syncwarp();   // own-warp P rows complete (A-frags read own rows only)

    float oacc[8][4];
#pragma unroll
    for (int nt = 0; nt < 8; nt++)
#pragma unroll
        for (int i = 0; i < 4; i++) oacc[nt][i] = 0.f;

#pragma unroll
    for (int kc = 0; kc < 8; kc++) {
        int kb2 = kc * 8;
        unsigned af[4];
        af[0] = Pw[(m0 + g) * A1_PS + kb2 + tig];
        af[1] = Pw[(m0 + 8 + g) * A1_PS + kb2 + tig];
        af[2] = Pw[(m0 + g) * A1_PS + kb2 + tig + 4];
        af[3] = Pw[(m0 + 8 + g) * A1_PS + kb2 + tig + 4];
#pragma unroll
        for (int nt = 0; nt < 8; nt++) {
            unsigned bf[2];
            bf[0] = Vw[(nt * 8 + g) * A1_VS + kb2 + tig];
            bf[1] = Vw[(nt * 8 + g) * A1_VS + kb2 + tig + 4];
            mma_f16(oacc[nt], af, bf);
        }
    }

    int a = n >> 4, b = n & 15;
    int s0 = m0 + g, s1 = m0 + 8 + g;
    size_t r0 = ((size_t)(s0 * 256 + b * 16 + a)) * 512 + h * 64;
    size_t r1 = ((size_t)(s1 * 256 + b * 16 + a)) * 512 + h * 64;
#pragma unroll
    for (int nt = 0; nt < 8; nt++) {
        int col = nt * 8 + 2 * tig;
        *(unsigned*)&o[r0 + col] = pack_h2(oacc[nt][0] * inv0, oacc[nt][1] * inv0);
        *(unsigned*)&o[r1 + col] = pack_h2(oacc[nt][2] * inv1, oacc[nt][3] * inv1);
    }
}

// ---------------- attention 2 via tf32 MMA: block per sb, 4 warps x 2 heads ------
#define H_STR 516
#define PW_STR 20
__global__ void __launch_bounds__(128) attn2_tc(const __half* __restrict__ xa,
                                                __half* __restrict__ o) {
    __shared__ unsigned hsu[16 * H_STR];
    __shared__ unsigned Pw2[4][16 * PW_STR];
    int sb = blockIdx.x;                      // s*16 + b
    int s_idx = sb >> 4, b_idx = sb & 15;
    int tid = threadIdx.x;
    int wid = tid >> 5, lane = tid & 31;
    int g = lane >> 2, tig = lane & 3;

    const uint4* src = (const uint4*)(xa + (size_t)sb * 16 * DD);  // 8 halfs each
#pragma unroll
    for (int i = 0; i < 8; i++) {
        int it = tid + 128 * i;               // 0..1023
        int r = it >> 6, c = it & 63;
        uint4 u = src[it];
        __half t[8];
        *(uint4*)t = u;
        uint4 w0 = make_uint4(f2tf32(__half2float(t[0])), f2tf32(__half2float(t[1])),
                              f2tf32(__half2float(t[2])), f2tf32(__half2float(t[3])));
        uint4 w1 = make_uint4(f2tf32(__half2float(t[4])), f2tf32(__half2float(t[5])),
                              f2tf32(__half2float(t[6])), f2tf32(__half2float(t[7])));
        *(uint4*)&hsu[r * H_STR + c * 8]     = w0;
        *(uint4*)&hsu[r * H_STR + c * 8 + 4] = w1;
    }
    __syncthreads();

    unsigned* ps = &Pw2[wid][0];
#pragma unroll
    for (int hh = 0; hh < 2; hh++) {
        int base = (wid * 2 + hh) * 64;

        float c[2][4];
#pragma unroll
        for (int nt = 0; nt < 2; nt++)
#pragma unroll
            for (int i = 0; i < 4; i++) c[nt][i] = 0.f;
#pragma unroll
        for (int kc = 0; kc < 8; kc++) {
            int kb = kc * 8;
            unsigned af[4];
            af[0] = hsu[g * H_STR + base + kb + tig];
            af[1] = hsu[(g + 8) * H_STR + base + kb + tig];
            af[2] = hsu[g * H_STR + base + kb + tig + 4];
            af[3] = hsu[(g + 8) * H_STR + base + kb + tig + 4];
#pragma unroll
            for (int nt = 0; nt < 2; nt++) {
                unsigned bf[2];
                bf[0] = hsu[(nt * 8 + g) * H_STR + base + kb + tig];
                bf[1] = hsu[(nt * 8 + g) * H_STR + base + kb + tig + 4];
                mma_tf32(c[nt], af, bf);
            }
        }

        float m0 = fmaxf(fmaxf(c[0][0], c[0][1]), fmaxf(c[1][0], c[1][1]));
        float m1 = fmaxf(fmaxf(c[0][2], c[0][3]), fmaxf(c[1][2], c[1][3]));
        m0 = fmaxf(m0, __shfl_xor_sync(0xffffffffu, m0, 1));
        m0 = fmaxf(m0, __shfl_xor_sync(0xffffffffu, m0, 2));
        m1 = fmaxf(m1, __shfl_xor_sync(0xffffffffu, m1, 1));
        m1 = fmaxf(m1, __shfl_xor_sync(0xffffffffu, m1, 2));
        float m0s = m0 * 0.125f, m1s = m1 * 0.125f;
        float e[2][4];
#pragma unroll
        for (int nt = 0; nt < 2; nt++) {
            e[nt][0] = __expf(c[nt][0] * 0.125f - m0s);
            e[nt][1] = __expf(c[nt][1] * 0.125f - m0s);
            e[nt][2] = __expf(c[nt][2] * 0.125f - m1s);
            e[nt][3] = __expf(c[nt][3] * 0.125f - m1s);
        }
        float s0 = e[0][0] + e[0][1] + e[1][0] + e[1][1];
        float s1 = e[0][2] + e[0][3] + e[1][2] + e[1][3];
        s0 += __shfl_xor_sync(0xffffffffu, s0, 1);
        s0 += __shfl_xor_sync(0xffffffffu, s0, 2);
        s1 += __shfl_xor_sync(0xffffffffu, s1, 1);
        s1 += __shfl_xor_sync(0xffffffffu, s1, 2);
        float inv0 = 1.f / s0, inv1 = 1.f / s1;

#pragma unroll
        for (int nt = 0; nt < 2; nt++) {
            int col = nt * 8 + 2 * tig;
            *(uint2*)&ps[g * PW_STR + col] =
                make_uint2(f2tf32(e[nt][0]), f2tf32(e[nt][1]));
            *(uint2*)&ps[(g + 8) * PW_STR + col] =
                make_uint2(f2tf32(e[nt][2]), f2tf32(e[nt][3]));
        }
        __syncwarp();

        float oc[8][4];
#pragma unroll
        for (int nt = 0; nt < 8; nt++)
#pragma unroll
            for (int i = 0; i < 4; i++) oc[nt][i] = 0.f;
#pragma unroll
        for (int kc = 0; kc < 2; kc++) {
            int kb = kc * 8;
            unsigned af[4];
            af[0] = ps[g * PW_STR + kb + tig];
            af[1] = ps[(g + 8) * PW_STR + kb + tig];
            af[2] = ps[g * PW_STR + kb + tig + 4];
            af[3] = ps[(g + 8) * PW_STR + kb + tig + 4];
#pragma unroll
            for (int nt = 0; nt < 8; nt++) {
                unsigned bf[2];
                bf[0] = hsu[(kb + tig) * H_STR + base + nt * 8 + g];
                bf[1] = hsu[(kb + tig + 4) * H_STR + base + nt * 8 + g];
                mma_tf32(oc[nt], af, bf);
            }
        }

        size_t r0 = ((size_t)((g * 16 + b_idx) * 128 + s_idx)) * 512 + base;
        size_t r1 = ((size_t)(((g + 8) * 16 + b_idx) * 128 + s_idx)) * 512 + base;
#pragma unroll
        for (int nt = 0; nt < 8; nt++) {
            int col = nt * 8 + 2 * tig;
            *(unsigned*)&o[r0 + col] = pack_h2(oc[nt][0] * inv0, oc[nt][1] * inv0);
            *(unsigned*)&o[r1 + col] = pack_h2(oc[nt][2] * inv1, oc[nt][3] * inv1);
        }
        __syncwarp();
    }
}

// =================================================================================
extern "C" void kernel_launch(void* const* d_in, const int* in_sizes, int n_in,
                              void* d_out, int out_size) {
    const float* query = (const float*)d_in[0];
    const float* key   = (const float*)d_in[1];
    const float* value = (const float*)d_in[2];
    // d_in[3] = mask (unused by reference)
    const float* padq  = (const float*)d_in[4];
    const float* padk  = (const float*)d_in[5];
    const float* Wq    = (const float*)d_in[6];
    const float* bq    = (const float*)d_in[7];
    const float* Wk    = (const float*)d_in[8];
    const float* bk    = (const float*)d_in[9];
    const float* Wv    = (const float*)d_in[10];
    const float* bv    = (const float*)d_in[11];
    const float* Wo    = (const float*)d_in[12];
    const float* bo    = (const float*)d_in[13];
    float* out = (float*)d_out;

    __half *xcq, *xck, *yqh, *ykh, *qh, *kh, *vh, *vh2, *xah, *xf, *Wh;
    cudaGetSymbolAddress((void**)&xcq, g_xcq);
    cudaGetSymbolAddress((void**)&xck, g_xck);
    cudaGetSymbolAddress((void**)&yqh, g_yqh);
    cudaGetSymbolAddress((void**)&ykh, g_ykh);
    cudaGetSymbolAddress((void**)&qh,  g_qh);
    cudaGetSymbolAddress((void**)&kh,  g_kh);
    cudaGetSymbolAddress((void**)&vh,  g_vh);
    cudaGetSymbolAddress((void**)&vh2, g_vh2);
    cudaGetSymbolAddress((void**)&xah, g_xah);
    cudaGetSymbolAddress((void**)&xf,  g_xf);
    cudaGetSymbolAddress((void**)&Wh,  g_Wh);

    const size_t WSZ = (size_t)DD * DD;

    // --- input conversions (fp16) ---
    const int conc_blocks = (NN*SC*128) / 256;   // 16896
    k_concat_cvt<<<conc_blocks, 256>>>(query, padq, xcq);
    k_concat_cvt<<<conc_blocks, 256>>>(key,   padk, xck);
    k_cvt_h<<<(int)(WSZ/4 + 255)/256, 256>>>(Wq, Wh + 0*WSZ, (int)(WSZ/4));
    k_cvt_h<<<(int)(WSZ/4 + 255)/256, 256>>>(Wk, Wh + 1*WSZ, (int)(WSZ/4));
    k_cvt_h<<<(int)(WSZ/4 + 255)/256, 256>>>(Wv, Wh + 2*WSZ, (int)(WSZ/4));
    k_cvt_h<<<(int)(WSZ/4 + 255)/256, 256>>>(Wo, Wh + 3*WSZ, (int)(WSZ/4));
    k_cvt_h<<<(NN*SS*DD/4 + 255)/256, 256>>>(value, vh, NN*SS*DD/4);

    // --- projections (fp16 tensor-core, fp16 outputs for intermediates) ---
    const int gemm_smem = 2 * 2 * GSTG * 4;      // 73728 B
    cudaFuncSetAttribute(gemm_h<__half>, cudaFuncAttributeMaxDynamicSharedMemorySize, gemm_smem);
    cudaFuncSetAttribute(gemm_h<float>,  cudaFuncAttributeMaxDynamicSharedMemorySize, gemm_smem);
    dim3 gproj(DD/128, (NN*SC)/128);             // (4, 264)
    gemm_h<__half><<<gproj, 256, gemm_smem>>>(xcq, Wh + 0*WSZ, bq, yqh);
    gemm_h<__half><<<gproj, 256, gemm_smem>>>(xck, Wh + 1*WSZ, bk, ykh);
    dim3 gv(DD/128, (NN*SS)/128);                // (4, 256)
    gemm_h<__half><<<gv, 256, gemm_smem>>>(vh, Wh + 2*WSZ, bv, vh2);

    // --- fused local window reweighting (weights + gather in one pass) ---
    cudaFuncSetAttribute(k_wg, cudaFuncAttributeMaxDynamicSharedMemorySize, WG_SMEM);
    k_wg<<<NN, 256, WG_SMEM>>>(yqh, qh);
    k_wg<<<NN, 256, WG_SMEM>>>(ykh, kh);

    // --- attention 1 (fp16 MMA; fp16 in/out; writes [S,B,A,D]) ---
    const int attn1_smem = 27136 * 2;            // 54272 B
    cudaFuncSetAttribute(attn1_h, cudaFuncAttributeMaxDynamicSharedMemorySize, attn1_smem);
    attn1_h<<<NN*HH, 256, attn1_smem>>>(qh, kh, vh2, xah);

    // --- attention 2 (tf32 core; fp16 in/out; writes [A,B,S,D]) ---
    attn2_tc<<<SS*BB, 128>>>(xah, xf);

    // --- output projection (fp32 out) ---
    gemm_h<float><<<gv, 256, gemm_smem>>>(xf, Wh + 3*WSZ, bo, out);
}

// round 13
// speedup vs baseline: 1.0510x; 1.0510x over previous
#include <cuda_runtime.h>
#include <cuda_fp16.h>
#include <cuda_bf16.h>
#include <math.h>
#include <stdint.h>

// Problem constants
#define AA 16
#define BB 16
#define SS 128
#define DD 512
#define NN 256        // A*B
#define LL 5
#define SC 132        // S + L - 1
#define HH 8
#define DK 64

// ---------------- scratch (device globals; no runtime allocation) ----------------
__device__ __half g_xcq[(size_t)NN*SC*DD];     // fp16 concat(q)
__device__ __half g_xck[(size_t)NN*SC*DD];     // fp16 concat(k)
__device__ __half g_yqh[(size_t)NN*SC*DD];     // fp16 projected q
__device__ __half g_ykh[(size_t)NN*SC*DD];     // fp16 projected k
__device__ float  g_wq [(size_t)NN*SS*LL];
__device__ float  g_wk [(size_t)NN*SS*LL];
__device__ __half g_qh [(size_t)NN*SS*DD];     // fp16 gathered q
__device__ __half g_kh [(size_t)NN*SS*DD];     // fp16 gathered k
__device__ __half g_vh [(size_t)NN*SS*DD];     // fp16 value (input cvt)
__device__ __half g_vh2[(size_t)NN*SS*DD];     // fp16 projected v
__device__ __half g_xah[(size_t)NN*SS*DD];     // fp16 [S,B,A,D]
__device__ __half g_xf [(size_t)NN*SS*DD];     // fp16 [A,B,S,D]
__device__ __half g_Wh [4*(size_t)DD*DD];      // fp16 Wq,Wk,Wv,Wo

// ---------------- helpers ---------------------------------------------------------
__device__ __forceinline__ unsigned f2tf32(float f) {
    unsigned u;
    asm("cvt.rna.tf32.f32 %0, %1;" : "=r"(u) : "f"(f));
    return u;
}

__device__ __forceinline__ void mma_tf32(float* d, const unsigned* a, const unsigned* b) {
    asm volatile(
        "mma.sync.aligned.m16n8k8.row.col.f32.tf32.tf32.f32 "
        "{%0,%1,%2,%3}, {%4,%5,%6,%7}, {%8,%9}, {%0,%1,%2,%3};"
        : "+f"(d[0]), "+f"(d[1]), "+f"(d[2]), "+f"(d[3])
        : "r"(a[0]), "r"(a[1]), "r"(a[2]), "r"(a[3]),
          "r"(b[0]), "r"(b[1]));
}

__device__ __forceinline__ void mma_f16(float* d, const unsigned* a, const unsigned* b) {
    asm volatile(
        "mma.sync.aligned.m16n8k16.row.col.f32.f16.f16.f32 "
        "{%0,%1,%2,%3}, {%4,%5,%6,%7}, {%8,%9}, {%0,%1,%2,%3};"
        : "+f"(d[0]), "+f"(d[1]), "+f"(d[2]), "+f"(d[3])
        : "r"(a[0]), "r"(a[1]), "r"(a[2]), "r"(a[3]),
          "r"(b[0]), "r"(b[1]));
}

__device__ __forceinline__ void cp16(unsigned* smem_dst, const void* gmem_src) {
    unsigned saddr = (unsigned)__cvta_generic_to_shared(smem_dst);
    asm volatile("cp.async.cg.shared.global [%0], [%1], 16;\n"
                 :: "r"(saddr), "l"(gmem_src));
}

__device__ __forceinline__ unsigned pack_h2(float a, float b) {
    __half2 h = __floats2half2_rn(a, b);
    return *(unsigned*)&h;
}

__device__ __forceinline__ void store2(float* C, size_t idx, float a, float b) {
    *(float2*)&C[idx] = make_float2(a, b);
}
__device__ __forceinline__ void store2(__half* C, size_t idx, float a, float b) {
    *(unsigned*)&C[idx] = pack_h2(a, b);
}

// ---------------- elementwise f32 -> fp16 -----------------------------------------
__global__ void k_cvt_h(const float* __restrict__ src, __half* __restrict__ dst, int n4) {
    int i = blockIdx.x * 256 + threadIdx.x;
    if (i < n4) {
        float4 v = ((const float4*)src)[i];
        ((uint2*)dst)[i] = make_uint2(pack_h2(v.x, v.y), pack_h2(v.z, v.w));
    }
}

// ---------------- 4 weight matrices -> fp16 in one launch -------------------------
// Each W: 512*512 = 262144 floats = 65536 float4 groups. Grid 1024 x 256 threads.
__global__ void k_cvt_w4(const float* __restrict__ w0, const float* __restrict__ w1,
                         const float* __restrict__ w2, const float* __restrict__ w3,
                         __half* __restrict__ dst) {
    int i = blockIdx.x * 256 + threadIdx.x;   // 0 .. 4*65536-1
    int wsel = i >> 16;
    int j = i & 65535;
    const float* src = (wsel == 0) ? w0 : (wsel == 1) ? w1 : (wsel == 2) ? w2 : w3;
    float4 v = ((const float4*)src)[j];
    ((uint2*)(dst + (size_t)wsel * 262144))[j] =
        make_uint2(pack_h2(v.x, v.y), pack_h2(v.z, v.w));
}

// ---------------- concat pad + x -> xc [N,132,D] fp16; q & k in one launch --------
__global__ void k_concat_cvt2(const float* __restrict__ xq, const float* __restrict__ pq,
                              const float* __restrict__ xk, const float* __restrict__ pk,
                              __half* __restrict__ xcq, __half* __restrict__ xck) {
    const float* x   = blockIdx.y ? xk : xq;
    const float* pad = blockIdx.y ? pk : pq;
    __half* xc       = blockIdx.y ? xck : xcq;
    int idx = blockIdx.x * 256 + threadIdx.x;     // float4 index; total N*SC*128
    int c   = idx & 127;
    int row = idx >> 7;
    int n = row / SC;
    int s = row - n * SC;
    const float4* src;
    if (s < LL - 1)
        src = (const float4*)pad + ((size_t)n*(LL-1) + s)*128 + c;
    else
        src = (const float4*)x   + ((size_t)n*SS + (s - (LL-1)))*128 + c;
    float4 v = *src;
    ((uint2*)xc)[idx] = make_uint2(pack_h2(v.x, v.y), pack_h2(v.z, v.w));
}

// ---------------- fp16 tensor-core GEMM: C[M,512] = A[M,512]@W[512,512]^T + bias --
// blockIdx.z selects problem (A0/W0/b0/C0 vs A1/W1/b1/C1) for batched launches.
#define GS 36
#define GSTG (128 * GS)
template<class T>
__global__ void __launch_bounds__(256) gemm_h2(const __half* __restrict__ A0,
                                               const __half* __restrict__ W0,
                                               const float* __restrict__ b0,
                                               T* __restrict__ C0,
                                               const __half* __restrict__ A1,
                                               const __half* __restrict__ W1,
                                               const float* __restrict__ b1,
                                               T* __restrict__ C1) {
    extern __shared__ unsigned sm[];   // [2 stages][As|Bs]
    const __half* A = blockIdx.z ? A1 : A0;
    const __half* W = blockIdx.z ? W1 : W0;
    const float* bias = blockIdx.z ? b1 : b0;
    T* C = blockIdx.z ? C1 : C0;

    int tid = threadIdx.x;
    int bm = blockIdx.y * 128;
    int bn = blockIdx.x * 128;
    int wid = tid >> 5, lane = tid & 31;
    int g = lane >> 2, tig = lane & 3;
    int wm = wid & 3, wn = wid >> 2;
    int m0 = wm * 32, n0 = wn * 64;

    const __half* Ab = A + (size_t)bm * 512;
    const __half* Wb = W + (size_t)bn * 512;

    float acc[2][8][4];
#pragma unroll
    for (int mt = 0; mt < 2; mt++)
#pragma unroll
        for (int nt = 0; nt < 8; nt++)
#pragma unroll
            for (int i = 0; i < 4; i++) acc[mt][nt][i] = 0.f;

#define PREFETCH(kt, stg)                                                        \
    {                                                                            \
        unsigned* sA = sm + (stg) * 2 * GSTG;                                    \
        unsigned* sB = sA + GSTG;                                                \
        _Pragma("unroll")                                                        \
        for (int i = 0; i < 4; i++) {                                            \
            int idx = tid + 256 * i;                                             \
            int r = idx >> 3, qd = idx & 7;                                      \
            cp16(sA + r * GS + qd * 4, Ab + (size_t)r * 512 + (kt) + qd * 8);    \
            cp16(sB + r * GS + qd * 4, Wb + (size_t)r * 512 + (kt) + qd * 8);    \
        }                                                                        \
        asm volatile("cp.async.commit_group;\n");                                \
    }

    PREFETCH(0, 0);

#pragma unroll 1
    for (int kt = 0; kt < 512; kt += 64) {
        int stg = (kt >> 6) & 1;
        if (kt + 64 < 512) {
            PREFETCH(kt + 64, stg ^ 1);
            asm volatile("cp.async.wait_group 1;\n");
        } else {
            asm volatile("cp.async.wait_group 0;\n");
        }
        __syncthreads();

        const unsigned* As = sm + stg * 2 * GSTG;
        const unsigned* Bs = As + GSTG;
#pragma unroll
        for (int kc = 0; kc < 4; kc++) {
            int kb2 = kc * 8;                 // word offset within row
            unsigned af[2][4], bf[8][2];
#pragma unroll
            for (int mt = 0; mt < 2; mt++) {
                int row = m0 + mt * 16 + g;
                af[mt][0] = As[row * GS + kb2 + tig];
                af[mt][1] = As[(row + 8) * GS + kb2 + tig];
                af[mt][2] = As[row * GS + kb2 + tig + 4];
                af[mt][3] = As[(row + 8) * GS + kb2 + tig + 4];
            }
#pragma unroll
            for (int nt = 0; nt < 8; nt++) {
                int col = n0 + nt * 8 + g;
                bf[nt][0] = Bs[col * GS + kb2 + tig];
                bf[nt][1] = Bs[col * GS + kb2 + tig + 4];
            }
#pragma unroll
            for (int mt = 0; mt < 2; mt++)
#pragma unroll
                for (int nt = 0; nt < 8; nt++)
                    mma_f16(acc[mt][nt], af[mt], bf[nt]);
        }
        __syncthreads();
    }
#undef PREFETCH

#pragma unroll
    for (int mt = 0; mt < 2; mt++) {
        int row = bm + m0 + mt * 16 + g;
#pragma unroll
        for (int nt = 0; nt < 8; nt++) {
            int col = bn + n0 + nt * 8 + 2 * tig;
            float c0 = bias[col], c1 = bias[col + 1];
            store2(C, (size_t)row * 512 + col, acc[mt][nt][0] + c0, acc[mt][nt][1] + c1);
            store2(C, (size_t)(row + 8) * 512 + col, acc[mt][nt][2] + c0, acc[mt][nt][3] + c1);
        }
    }
}

// ---------------- local-window softmax weights (q & k in one launch) --------------
__global__ void k_weights2(const __half* __restrict__ yq, const __half* __restrict__ yk,
                           float* __restrict__ wq, float* __restrict__ wk) {
    const __half* y = blockIdx.y ? yk : yq;
    float* w        = blockIdx.y ? wk : wq;
    int gw = blockIdx.x * 4 + (threadIdx.x >> 5);   // warp -> (n,s)
    int lane = threadIdx.x & 31;
    int n = gw >> 7;
    int s = gw & 127;
    const __half2* base = (const __half2*)(y + (size_t)n * SC * DD);
    const __half2* cen  = base + (size_t)(s + LL - 1) * 256;
    float d0=0.f,d1=0.f,d2=0.f,d3=0.f,d4=0.f;
    for (int i = lane; i < 256; i += 32) {
        float2 cv = __half22float2(cen[i]);
        float2 v0 = __half22float2(base[(s+0)*256 + i]);
        float2 v1 = __half22float2(base[(s+1)*256 + i]);
        float2 v2 = __half22float2(base[(s+2)*256 + i]);
        float2 v3 = __half22float2(base[(s+3)*256 + i]);
        float2 v4 = __half22float2(base[(s+4)*256 + i]);
        d0 += cv.x*v0.x + cv.y*v0.y;
        d1 += cv.x*v1.x + cv.y*v1.y;
        d2 += cv.x*v2.x + cv.y*v2.y;
        d3 += cv.x*v3.x + cv.y*v3.y;
        d4 += cv.x*v4.x + cv.y*v4.y;
    }
#pragma unroll
    for (int off = 16; off; off >>= 1) {
        d0 += __shfl_xor_sync(0xffffffffu, d0, off);
        d1 += __shfl_xor_sync(0xffffffffu, d1, off);
        d2 += __shfl_xor_sync(0xffffffffu, d2, off);
        d3 += __shfl_xor_sync(0xffffffffu, d3, off);
        d4 += __shfl_xor_sync(0xffffffffu, d4, off);
    }
    if (lane == 0) {
        const float sc = 0.044194173824159216f;  // 1/sqrt(512)
        float s0 = d0*sc, s1 = d1*sc, s2 = d2*sc, s3 = d3*sc, s4 = d4*sc;
        float m = fmaxf(fmaxf(fmaxf(s0,s1), fmaxf(s2,s3)), s4);
        float e0 = __expf(s0-m), e1 = __expf(s1-m), e2 = __expf(s2-m),
              e3 = __expf(s3-m), e4 = __expf(s4-m);
        float inv = 1.f / (e0+e1+e2+e3+e4);
        float* wp = w + (size_t)gw * LL;
        wp[0]=e0*inv; wp[1]=e1*inv; wp[2]=e2*inv; wp[3]=e3*inv; wp[4]=e4*inv;
    }
}

// ---------------- scrambled-reshape gather (q & k in one launch) ------------------
__global__ void k_gather2(const __half* __restrict__ yq, const __half* __restrict__ yk,
                          const float* __restrict__ wq, const float* __restrict__ wk,
                          __half* __restrict__ oq, __half* __restrict__ ok) {
    const __half* y = blockIdx.y ? yk : yq;
    const float* w  = blockIdx.y ? wk : wq;
    __half* out     = blockIdx.y ? ok : oq;
    int ns = blockIdx.x;           // n*128 + s
    int n = ns >> 7;
    int s = ns & 127;
    float coef[LL];
    int   rowi[LL];
#pragma unroll
    for (int l = 0; l < LL; l++) {
        int f  = l * SS + s;
        int sp = f / 5;
        int lp = f - sp * 5;
        coef[l] = w[((size_t)n * SS + sp) * LL + lp];
        rowi[l] = sp + lp;
    }
    const uint2* yb = (const uint2*)y + (size_t)n * SC * 128;  // 128 uint2 per row
    int c = threadIdx.x;   // 0..127 (4 halfs each)
    float4 acc = make_float4(0.f,0.f,0.f,0.f);
#pragma unroll
    for (int l = 0; l < LL; l++) {
        uint2 u = yb[(size_t)rowi[l] * 128 + c];
        float2 f0 = __half22float2(*(__half2*)&u.x);
        float2 f1 = __half22float2(*(__half2*)&u.y);
        acc.x += coef[l]*f0.x; acc.y += coef[l]*f0.y;
        acc.z += coef[l]*f1.x; acc.w += coef[l]*f1.y;
    }
    ((uint2*)out)[(size_t)ns * 128 + c] =
        make_uint2(pack_h2(acc.x, acc.y), pack_h2(acc.z, acc.w));
}

// ---------------- attention 1 via fp16 MMA: per (n,h) block, S=128, dk=64 --------
#define A1_QS 36    // word stride Q/K rows (72 halfs)
#define A1_PS 68    // word stride P rows (136 halfs)
#define A1_VS 68    // word stride Vt rows (136 halfs)
__global__ void __launch_bounds__(256) attn1_h(const __half* __restrict__ q,
                                               const __half* __restrict__ k,
                                               const __half* __restrict__ v,
                                               __half* __restrict__ o) {
    extern __shared__ __half hs[];
    __half* Qh = hs;
    __half* Kh = hs + 9216;
    __half* Vt = hs + 18432;
    unsigned* Qw = (unsigned*)Qh;
    unsigned* Kw = (unsigned*)Kh;
    unsigned* Pw = (unsigned*)hs;      // overlay after QK phase
    unsigned* Vw = (unsigned*)Vt;

    int n = blockIdx.x >> 3, h = blockIdx.x & 7;
    int tid = threadIdx.x;
    int lane = tid & 31;
    int g = lane >> 2, tig = lane & 3;
    int m0 = (tid >> 5) * 16;          // warp -> 16 rows

    // stage Q,K: raw fp16 copies (8 halfs/thread/iter)
#pragma unroll
    for (int i = 0; i < 4; i++) {
        int idx = tid + 256 * i;       // 0..1023 = 128 s x 8 dq
        int s = idx >> 3, dq = idx & 7;
        size_t goff = ((size_t)(n * 128 + s)) * 512 + h * 64 + dq * 8;
        *(uint4*)&Qh[s * 72 + dq * 8] = *(const uint4*)(q + goff);
        *(uint4*)&Kh[s * 72 + dq * 8] = *(const uint4*)(k + goff);
    }
    // stage V transposed [d][s] (4 halfs/thread/iter)
#pragma unroll
    for (int i = 0; i < 8; i++) {
        int idx = tid + 256 * i;       // 0..2047 = 128 s x 16 dq
        int s = idx >> 4, dq = idx & 15;
        size_t goff = ((size_t)(n * 128 + s)) * 512 + h * 64 + dq * 4;
        uint2 u = *(const uint2*)(v + goff);
        __half t[4];
        *(uint2*)t = u;
        int d0 = dq * 4;
        Vt[(d0+0) * 136 + s] = t[0];
        Vt[(d0+1) * 136 + s] = t[1];
        Vt[(d0+2) * 136 + s] = t[2];
        Vt[(d0+3) * 136 + s] = t[3];
    }
    __syncthreads();

    float acc[16][4];
#pragma unroll
    for (int nt = 0; nt < 16; nt++)
#pragma unroll
        for (int i = 0; i < 4; i++) acc[nt][i] = 0.f;

#pragma unroll
    for (int kc = 0; kc < 4; kc++) {   // K=64 -> 4 x k16
        int kb2 = kc * 8;
        unsigned af[4];
        af[0] = Qw[(m0 + g) * A1_QS + kb2 + tig];
        af[1] = Qw[(m0 + 8 + g) * A1_QS + kb2 + tig];
        af[2] = Qw[(m0 + g) * A1_QS + kb2 + tig + 4];
        af[3] = Qw[(m0 + 8 + g) * A1_QS + kb2 + tig + 4];
#pragma unroll
        for (int nt = 0; nt < 16; nt++) {
            unsigned bf[2];
            bf[0] = Kw[(nt * 8 + g) * A1_QS + kb2 + tig];
            bf[1] = Kw[(nt * 8 + g) * A1_QS + kb2 + tig + 4];
            mma_f16(acc[nt], af, bf);
        }
    }
    __syncthreads();   // Q/K dead in all warps -> safe to overlay P

    float mx0 = -1e30f, mx1 = -1e30f;
#pragma unroll
    for (int nt = 0; nt < 16; nt++) {
        mx0 = fmaxf(mx0, fmaxf(acc[nt][0], acc[nt][1]));
        mx1 = fmaxf(mx1, fmaxf(acc[nt][2], acc[nt][3]));
    }
    mx0 = fmaxf(mx0, __shfl_xor_sync(0xffffffffu, mx0, 1));
    mx0 = fmaxf(mx0, __shfl_xor_sync(0xffffffffu, mx0, 2));
    mx1 = fmaxf(mx1, __shfl_xor_sync(0xffffffffu, mx1, 1));
    mx1 = fmaxf(mx1, __shfl_xor_sync(0xffffffffu, mx1, 2));
    float sum0 = 0.f, sum1 = 0.f;
#pragma unroll
    for (int nt = 0; nt < 16; nt++) {
        float e0 = __expf(0.125f * (acc[nt][0] - mx0));
        float e1 = __expf(0.125f * (acc[nt][1] - mx0));
        float e2 = __expf(0.125f * (acc[nt][2] - mx1));
        float e3 = __expf(0.125f * (acc[nt][3] - mx1));
        sum0 += e0 + e1;
        sum1 += e2 + e3;
        int cw = nt * 4 + tig;         // word col = (nt*8 + 2tig)/2
        Pw[(m0 + g) * A1_PS + cw]     = pack_h2(e0, e1);
        Pw[(m0 + 8 + g) * A1_PS + cw] = pack_h2(e2, e3);
    }
    sum0 += __shfl_xor_sync(0xffffffffu, sum0, 1);
    sum0 += __shfl_xor_sync(0xffffffffu, sum0, 2);
    sum1 += __shfl_xor_sync(0xffffffffu, sum1, 1);
    sum1 += __shfl_xor_sync(0xffffffffu, sum1, 2);
    float inv0 = 1.f / sum0, inv1 = 1.f / sum1;
    __syncwarp();   // own-warp P rows complete (A-frags read own rows only)

    float oacc[8][4];
#pragma unroll
    for (int nt = 0; nt < 8; nt++)
#pragma unroll
        for (int i = 0; i < 4; i++) oacc[nt][i] = 0.f;

#pragma unroll
    for (int kc = 0; kc < 8; kc++) {
        int kb2 = kc * 8;
        unsigned af[4];
        af[0] = Pw[(m0 + g) * A1_PS + kb2 + tig];
        af[1] = Pw[(m0 + 8 + g) * A1_PS + kb2 + tig];
        af[2] = Pw[(m0 + g) * A1_PS + kb2 + tig + 4];
        af[3] = Pw[(m0 + 8 + g) * A1_PS + kb2 + tig + 4];
#pragma unroll
        for (int nt = 0; nt < 8; nt++) {
            unsigned bf[2];
            bf[0] = Vw[(nt * 8 + g) * A1_VS + kb2 + tig];
            bf[1] = Vw[(nt * 8 + g) * A1_VS + kb2 + tig + 4];
            mma_f16(oacc[nt], af, bf);
        }
    }

    int a = n >> 4, b = n & 15;
    int s0 = m0 + g, s1 = m0 + 8 + g;
    size_t r0 = ((size_t)(s0 * 256 + b * 16 + a)) * 512 + h * 64;
    size_t r1 = ((size_t)(s1 * 256 + b * 16 + a)) * 512 + h * 64;
#pragma unroll
    for (int nt = 0; nt < 8; nt++) {
        int col = nt * 8 + 2 * tig;
        *(unsigned*)&o[r0 + col] = pack_h2(oacc[nt][0] * inv0, oacc[nt][1] * inv0);
        *(unsigned*)&o[r1 + col] = pack_h2(oacc[nt][2] * inv1, oacc[nt][3] * inv1);
    }
}

// ---------------- attention 2 via tf32 MMA: block per sb, 4 warps x 2 heads ------
#define H_STR 516
#define PW_STR 20
__global__ void __launch_bounds__(128) attn2_tc(const __half* __restrict__ xa,
                                                __half* __restrict__ o) {
    __shared__ unsigned hsu[16 * H_STR];
    __shared__ unsigned Pw2[4][16 * PW_STR];
    int sb = blockIdx.x;                      // s*16 + b
    int s_idx = sb >> 4, b_idx = sb & 15;
    int tid = threadIdx.x;
    int wid = tid >> 5, lane = tid & 31;
    int g = lane >> 2, tig = lane & 3;

    const uint4* src = (const uint4*)(xa + (size_t)sb * 16 * DD);  // 8 halfs each
#pragma unroll
    for (int i = 0; i < 8; i++) {
        int it = tid + 128 * i;               // 0..1023
        int r = it >> 6, c = it & 63;
        uint4 u = src[it];
        __half t[8];
        *(uint4*)t = u;
        uint4 w0 = make_uint4(f2tf32(__half2float(t[0])), f2tf32(__half2float(t[1])),
                              f2tf32(__half2float(t[2])), f2tf32(__half2float(t[3])));
        uint4 w1 = make_uint4(f2tf32(__half2float(t[4])), f2tf32(__half2float(t[5])),
                              f2tf32(__half2float(t[6])), f2tf32(__half2float(t[7])));
        *(uint4*)&hsu[r * H_STR + c * 8]     = w0;
        *(uint4*)&hsu[r * H_STR + c * 8 + 4] = w1;
    }
    __syncthreads();

    unsigned* ps = &Pw2[wid][0];
#pragma unroll
    for (int hh = 0; hh < 2; hh++) {
        int base = (wid * 2 + hh) * 64;

        float c[2][4];
#pragma unroll
        for (int nt = 0; nt < 2; nt++)
#pragma unroll
            for (int i = 0; i < 4; i++) c[nt][i] = 0.f;
#pragma unroll
        for (int kc = 0; kc < 8; kc++) {
            int kb = kc * 8;
            unsigned af[4];
            af[0] = hsu[g * H_STR + base + kb + tig];
            af[1] = hsu[(g + 8) * H_STR + base + kb + tig];
            af[2] = hsu[g * H_STR + base + kb + tig + 4];
            af[3] = hsu[(g + 8) * H_STR + base + kb + tig + 4];
#pragma unroll
            for (int nt = 0; nt < 2; nt++) {
                unsigned bf[2];
                bf[0] = hsu[(nt * 8 + g) * H_STR + base + kb + tig];
                bf[1] = hsu[(nt * 8 + g) * H_STR + base + kb + tig + 4];
                mma_tf32(c[nt], af, bf);
            }
        }

        float m0 = fmaxf(fmaxf(c[0][0], c[0][1]), fmaxf(c[1][0], c[1][1]));
        float m1 = fmaxf(fmaxf(c[0][2], c[0][3]), fmaxf(c[1][2], c[1][3]));
        m0 = fmaxf(m0, __shfl_xor_sync(0xffffffffu, m0, 1));
        m0 = fmaxf(m0, __shfl_xor_sync(0xffffffffu, m0, 2));
        m1 = fmaxf(m1, __shfl_xor_sync(0xffffffffu, m1, 1));
        m1 = fmaxf(m1, __shfl_xor_sync(0xffffffffu, m1, 2));
        float m0s = m0 * 0.125f, m1s = m1 * 0.125f;
        float e[2][4];
#pragma unroll
        for (int nt = 0; nt < 2; nt++) {
            e[nt][0] = __expf(c[nt][0] * 0.125f - m0s);
            e[nt][1] = __expf(c[nt][1] * 0.125f - m0s);
            e[nt][2] = __expf(c[nt][2] * 0.125f - m1s);
            e[nt][3] = __expf(c[nt][3] * 0.125f - m1s);
        }
        float s0 = e[0][0] + e[0][1] + e[1][0] + e[1][1];
        float s1 = e[0][2] + e[0][3] + e[1][2] + e[1][3];
        s0 += __shfl_xor_sync(0xffffffffu, s0, 1);
        s0 += __shfl_xor_sync(0xffffffffu, s0, 2);
        s1 += __shfl_xor_sync(0xffffffffu, s1, 1);
        s1 += __shfl_xor_sync(0xffffffffu, s1, 2);
        float inv0 = 1.f / s0, inv1 = 1.f / s1;

#pragma unroll
        for (int nt = 0; nt < 2; nt++) {
            int col = nt * 8 + 2 * tig;
            *(uint2*)&ps[g * PW_STR + col] =
                make_uint2(f2tf32(e[nt][0]), f2tf32(e[nt][1]));
            *(uint2*)&ps[(g + 8) * PW_STR + col] =
                make_uint2(f2tf32(e[nt][2]), f2tf32(e[nt][3]));
        }
        __syncwarp();

        float oc[8][4];
#pragma unroll
        for (int nt = 0; nt < 8; nt++)
#pragma unroll
            for (int i = 0; i < 4; i++) oc[nt][i] = 0.f;
#pragma unroll
        for (int kc = 0; kc < 2; kc++) {
            int kb = kc * 8;
            unsigned af[4];
            af[0] = ps[g * PW_STR + kb + tig];
            af[1] = ps[(g + 8) * PW_STR + kb + tig];
            af[2] = ps[g * PW_STR + kb + tig + 4];
            af[3] = ps[(g + 8) * PW_STR + kb + tig + 4];
#pragma unroll
            for (int nt = 0; nt < 8; nt++) {
                unsigned bf[2];
                bf[0] = hsu[(kb + tig) * H_STR + base + nt * 8 + g];
                bf[1] = hsu[(kb + tig + 4) * H_STR + base + nt * 8 + g];
                mma_tf32(oc[nt], af, bf);
            }
        }

        size_t r0 = ((size_t)((g * 16 + b_idx) * 128 + s_idx)) * 512 + base;
        size_t r1 = ((size_t)(((g + 8) * 16 + b_idx) * 128 + s_idx)) * 512 + base;
#pragma unroll
        for (int nt = 0; nt < 8; nt++) {
            int col = nt * 8 + 2 * tig;
            *(unsigned*)&o[r0 + col] = pack_h2(oc[nt][0] * inv0, oc[nt][1] * inv0);
            *(unsigned*)&o[r1 + col] = pack_h2(oc[nt][2] * inv1, oc[nt][3] * inv1);
        }
        __syncwarp();
    }
}

// =================================================================================
extern "C" void kernel_launch(void* const* d_in, const int* in_sizes, int n_in,
                              void* d_out, int out_size) {
    const float* query = (const float*)d_in[0];
    const float* key   = (const float*)d_in[1];
    const float* value = (const float*)d_in[2];
    // d_in[3] = mask (unused by reference)
    const float* padq  = (const float*)d_in[4];
    const float* padk  = (const float*)d_in[5];
    const float* Wq    = (const float*)d_in[6];
    const float* bq    = (const float*)d_in[7];
    const float* Wk    = (const float*)d_in[8];
    const float* bk    = (const float*)d_in[9];
    const float* Wv    = (const float*)d_in[10];
    const float* bv    = (const float*)d_in[11];
    const float* Wo    = (const float*)d_in[12];
    const float* bo    = (const float*)d_in[13];
    float* out = (float*)d_out;

    __half *xcq, *xck, *yqh, *ykh, *qh, *kh, *vh, *vh2, *xah, *xf, *Wh;
    float *wq, *wk;
    cudaGetSymbolAddress((void**)&xcq, g_xcq);
    cudaGetSymbolAddress((void**)&xck, g_xck);
    cudaGetSymbolAddress((void**)&yqh, g_yqh);
    cudaGetSymbolAddress((void**)&ykh, g_ykh);
    cudaGetSymbolAddress((void**)&wq,  g_wq);
    cudaGetSymbolAddress((void**)&wk,  g_wk);
    cudaGetSymbolAddress((void**)&qh,  g_qh);
    cudaGetSymbolAddress((void**)&kh,  g_kh);
    cudaGetSymbolAddress((void**)&vh,  g_vh);
    cudaGetSymbolAddress((void**)&vh2, g_vh2);
    cudaGetSymbolAddress((void**)&xah, g_xah);
    cudaGetSymbolAddress((void**)&xf,  g_xf);
    cudaGetSymbolAddress((void**)&Wh,  g_Wh);

    const size_t WSZ = (size_t)DD * DD;

    // --- input conversions (fp16), batched ---
    dim3 gconc((NN*SC*128) / 256, 2);            // (16896, 2)
    k_concat_cvt2<<<gconc, 256>>>(query, padq, key, padk, xcq, xck);
    k_cvt_w4<<<1024, 256>>>(Wq, Wk, Wv, Wo, Wh);
    k_cvt_h<<<(NN*SS*DD/4 + 255)/256, 256>>>(value, vh, NN*SS*DD/4);

    // --- projections (fp16 tensor-core; Q & K batched in one launch) ---
    const int gemm_smem = 2 * 2 * GSTG * 4;      // 73728 B
    cudaFuncSetAttribute(gemm_h2<__half>, cudaFuncAttributeMaxDynamicSharedMemorySize, gemm_smem);
    cudaFuncSetAttribute(gemm_h2<float>,  cudaFuncAttributeMaxDynamicSharedMemorySize, gemm_smem);
    dim3 gqk(DD/128, (NN*SC)/128, 2);            // (4, 264, 2)
    gemm_h2<__half><<<gqk, 256, gemm_smem>>>(xcq, Wh + 0*WSZ, bq, yqh,
                                             xck, Wh + 1*WSZ, bk, ykh);
    dim3 gv(DD/128, (NN*SS)/128, 1);             // (4, 256, 1)
    gemm_h2<__half><<<gv, 256, gemm_smem>>>(vh, Wh + 2*WSZ, bv, vh2,
                                            vh, Wh + 2*WSZ, bv, vh2);

    // --- local window reweighting (q & k batched) ---
    dim3 gwt((NN*SS)/4, 2);
    k_weights2<<<gwt, 128>>>(yqh, ykh, wq, wk);
    dim3 ggt(NN*SS, 2);
    k_gather2<<<ggt, 128>>>(yqh, ykh, wq, wk, qh, kh);

    // --- attention 1 (fp16 MMA; fp16 in/out; writes [S,B,A,D]) ---
    const int attn1_smem = 27136 * 2;            // 54272 B
    cudaFuncSetAttribute(attn1_h, cudaFuncAttributeMaxDynamicSharedMemorySize, attn1_smem);
    attn1_h<<<NN*HH, 256, attn1_smem>>>(qh, kh, vh2, xah);

    // --- attention 2 (tf32 core; fp16 in/out; writes [A,B,S,D]) ---
    attn2_tc<<<SS*BB, 128>>>(xah, xf);

    // --- output projection (fp32 out) ---
    gemm_h2<float><<<gv, 256, gemm_smem>>>(xf, Wh + 3*WSZ, bo, out,
                                           xf, Wh + 3*WSZ, bo, out);
}

// round 14
// speedup vs baseline: 1.0824x; 1.0299x over previous
#include <cuda_runtime.h>
#include <cuda_fp16.h>
#include <cuda_bf16.h>
#include <math.h>
#include <stdint.h>

// Problem constants
#define AA 16
#define BB 16
#define SS 128
#define DD 512
#define NN 256        // A*B
#define LL 5
#define SC 132        // S + L - 1
#define HH 8
#define DK 64

// ---------------- scratch (device globals; no runtime allocation) ----------------
__device__ __half g_xcq[(size_t)NN*SC*DD];     // fp16 concat(q)
__device__ __half g_xck[(size_t)NN*SC*DD];     // fp16 concat(k)
__device__ __half g_yqh[(size_t)NN*SC*DD];     // fp16 projected q
__device__ __half g_ykh[(size_t)NN*SC*DD];     // fp16 projected k
__device__ float  g_wq [(size_t)NN*SS*LL];
__device__ float  g_wk [(size_t)NN*SS*LL];
__device__ __half g_qh [(size_t)NN*SS*DD];     // fp16 gathered q
__device__ __half g_kh [(size_t)NN*SS*DD];     // fp16 gathered k
__device__ __half g_vh [(size_t)NN*SS*DD];     // fp16 value (input cvt)
__device__ __half g_vh2[(size_t)NN*SS*DD];     // fp16 projected v
__device__ __half g_xah[(size_t)NN*SS*DD];     // fp16 [S,B,A,D]
__device__ __half g_xf [(size_t)NN*SS*DD];     // fp16 [A,B,S,D]
__device__ __half g_Wh [4*(size_t)DD*DD];      // fp16 Wq,Wk,Wv,Wo

// ---------------- helpers ---------------------------------------------------------
__device__ __forceinline__ unsigned f2tf32(float f) {
    unsigned u;
    asm("cvt.rna.tf32.f32 %0, %1;" : "=r"(u) : "f"(f));
    return u;
}

__device__ __forceinline__ void mma_tf32(float* d, const unsigned* a, const unsigned* b) {
    asm volatile(
        "mma.sync.aligned.m16n8k8.row.col.f32.tf32.tf32.f32 "
        "{%0,%1,%2,%3}, {%4,%5,%6,%7}, {%8,%9}, {%0,%1,%2,%3};"
        : "+f"(d[0]), "+f"(d[1]), "+f"(d[2]), "+f"(d[3])
        : "r"(a[0]), "r"(a[1]), "r"(a[2]), "r"(a[3]),
          "r"(b[0]), "r"(b[1]));
}

__device__ __forceinline__ void mma_f16(float* d, const unsigned* a, const unsigned* b) {
    asm volatile(
        "mma.sync.aligned.m16n8k16.row.col.f32.f16.f16.f32 "
        "{%0,%1,%2,%3}, {%4,%5,%6,%7}, {%8,%9}, {%0,%1,%2,%3};"
        : "+f"(d[0]), "+f"(d[1]), "+f"(d[2]), "+f"(d[3])
        : "r"(a[0]), "r"(a[1]), "r"(a[2]), "r"(a[3]),
          "r"(b[0]), "r"(b[1]));
}

__device__ __forceinline__ void ldsm4(unsigned& r0, unsigned& r1, unsigned& r2,
                                      unsigned& r3, unsigned addr) {
    asm volatile("ldmatrix.sync.aligned.m8n8.x4.shared.b16 {%0,%1,%2,%3}, [%4];"
                 : "=r"(r0), "=r"(r1), "=r"(r2), "=r"(r3) : "r"(addr));
}

__device__ __forceinline__ void cp16(unsigned* smem_dst, const void* gmem_src) {
    unsigned saddr = (unsigned)__cvta_generic_to_shared(smem_dst);
    asm volatile("cp.async.cg.shared.global [%0], [%1], 16;\n"
                 :: "r"(saddr), "l"(gmem_src));
}

__device__ __forceinline__ unsigned pack_h2(float a, float b) {
    __half2 h = __floats2half2_rn(a, b);
    return *(unsigned*)&h;
}

__device__ __forceinline__ void store2(float* C, size_t idx, float a, float b) {
    *(float2*)&C[idx] = make_float2(a, b);
}
__device__ __forceinline__ void store2(__half* C, size_t idx, float a, float b) {
    *(unsigned*)&C[idx] = pack_h2(a, b);
}

// ---------------- elementwise f32 -> fp16 -----------------------------------------
__global__ void k_cvt_h(const float* __restrict__ src, __half* __restrict__ dst, int n4) {
    int i = blockIdx.x * 256 + threadIdx.x;
    if (i < n4) {
        float4 v = ((const float4*)src)[i];
        ((uint2*)dst)[i] = make_uint2(pack_h2(v.x, v.y), pack_h2(v.z, v.w));
    }
}

// ---------------- 4 weight matrices -> fp16 in one launch -------------------------
__global__ void k_cvt_w4(const float* __restrict__ w0, const float* __restrict__ w1,
                         const float* __restrict__ w2, const float* __restrict__ w3,
                         __half* __restrict__ dst) {
    int i = blockIdx.x * 256 + threadIdx.x;   // 0 .. 4*65536-1
    int wsel = i >> 16;
    int j = i & 65535;
    const float* src = (wsel == 0) ? w0 : (wsel == 1) ? w1 : (wsel == 2) ? w2 : w3;
    float4 v = ((const float4*)src)[j];
    ((uint2*)(dst + (size_t)wsel * 262144))[j] =
        make_uint2(pack_h2(v.x, v.y), pack_h2(v.z, v.w));
}

// ---------------- concat pad + x -> xc [N,132,D] fp16; q & k in one launch --------
__global__ void k_concat_cvt2(const float* __restrict__ xq, const float* __restrict__ pq,
                              const float* __restrict__ xk, const float* __restrict__ pk,
                              __half* __restrict__ xcq, __half* __restrict__ xck) {
    const float* x   = blockIdx.y ? xk : xq;
    const float* pad = blockIdx.y ? pk : pq;
    __half* xc       = blockIdx.y ? xck : xcq;
    int idx = blockIdx.x * 256 + threadIdx.x;     // float4 index; total N*SC*128
    int c   = idx & 127;
    int row = idx >> 7;
    int n = row / SC;
    int s = row - n * SC;
    const float4* src;
    if (s < LL - 1)
        src = (const float4*)pad + ((size_t)n*(LL-1) + s)*128 + c;
    else
        src = (const float4*)x   + ((size_t)n*SS + (s - (LL-1)))*128 + c;
    float4 v = *src;
    ((uint2*)xc)[idx] = make_uint2(pack_h2(v.x, v.y), pack_h2(v.z, v.w));
}

// ---------------- fp16 tensor-core GEMM w/ ldmatrix fragments ---------------------
// C[M,512] = A[M,512]@W[512,512]^T + bias. blockIdx.z selects problem.
// 128x128 tile, BK=64 halfs, 2-stage cp.async, 8 warps (4m x 2n), warp tile 32x64.
// Smem rows: 64 halfs + 8 pad = 72 halfs (144 B).
#define GS 36
#define GSTG (128 * GS)
#define ROWB 144
template<class T>
__global__ void __launch_bounds__(256) gemm_h2(const __half* __restrict__ A0,
                                               const __half* __restrict__ W0,
                                               const float* __restrict__ b0,
                                               T* __restrict__ C0,
                                               const __half* __restrict__ A1,
                                               const __half* __restrict__ W1,
                                               const float* __restrict__ b1,
                                               T* __restrict__ C1) {
    extern __shared__ unsigned sm[];   // [2 stages][As|Bs]
    const __half* A = blockIdx.z ? A1 : A0;
    const __half* W = blockIdx.z ? W1 : W0;
    const float* bias = blockIdx.z ? b1 : b0;
    T* C = blockIdx.z ? C1 : C0;

    int tid = threadIdx.x;
    int bm = blockIdx.y * 128;
    int bn = blockIdx.x * 128;
    int wid = tid >> 5, lane = tid & 31;
    int g = lane >> 2, tig = lane & 3;
    int wm = wid & 3, wn = wid >> 2;
    int m0 = wm * 32, n0 = wn * 64;

    const __half* Ab = A + (size_t)bm * 512;
    const __half* Wb = W + (size_t)bn * 512;

    // ldmatrix per-lane intra-tile byte offsets
    int lrow = lane & 7;
    unsigned a_row = m0 + lrow + ((lane & 8) ? 8 : 0);
    unsigned a_kb  = ((lane & 16) ? 8 : 0) * 2;
    unsigned b_row = lrow + ((lane & 16) ? 8 : 0);
    unsigned b_kb  = ((lane & 8) ? 8 : 0) * 2;
    unsigned sbase = (unsigned)__cvta_generic_to_shared(sm);
    unsigned aoff0 = a_row * ROWB + a_kb;            // + mt*16*ROWB + kc*32
    unsigned boff0 = (n0 + b_row) * ROWB + b_kb;     // + p*16*ROWB + kc*32

    float acc[2][8][4];
#pragma unroll
    for (int mt = 0; mt < 2; mt++)
#pragma unroll
        for (int nt = 0; nt < 8; nt++)
#pragma unroll
            for (int i = 0; i < 4; i++) acc[mt][nt][i] = 0.f;

#define PREFETCH(kt, stg)                                                        \
    {                                                                            \
        unsigned* sA = sm + (stg) * 2 * GSTG;                                    \
        unsigned* sB = sA + GSTG;                                                \
        _Pragma("unroll")                                                        \
        for (int i = 0; i < 4; i++) {                                            \
            int idx = tid + 256 * i;                                             \
            int r = idx >> 3, qd = idx & 7;                                      \
            cp16(sA + r * GS + qd * 4, Ab + (size_t)r * 512 + (kt) + qd * 8);    \
            cp16(sB + r * GS + qd * 4, Wb + (size_t)r * 512 + (kt) + qd * 8);    \
        }                                                                        \
        asm volatile("cp.async.commit_group;\n");                                \
    }

    PREFETCH(0, 0);

#pragma unroll 1
    for (int kt = 0; kt < 512; kt += 64) {
        int stg = (kt >> 6) & 1;
        if (kt + 64 < 512) {
            PREFETCH(kt + 64, stg ^ 1);
            asm volatile("cp.async.wait_group 1;\n");
        } else {
            asm volatile("cp.async.wait_group 0;\n");
        }
        __syncthreads();

        unsigned aA = sbase + stg * 2 * GSTG * 4 + aoff0;
        unsigned aB = sbase + (stg * 2 + 1) * GSTG * 4 + boff0;
#pragma unroll
        for (int kc = 0; kc < 4; kc++) {
            unsigned kadd = kc * 32;   // 16 halfs
            unsigned af[2][4];
            ldsm4(af[0][0], af[0][1], af[0][2], af[0][3], aA + kadd);
            ldsm4(af[1][0], af[1][1], af[1][2], af[1][3], aA + 16 * ROWB + kadd);
#pragma unroll
            for (int p = 0; p < 4; p++) {
                unsigned r0, r1, r2, r3;
                ldsm4(r0, r1, r2, r3, aB + p * 16 * ROWB + kadd);
                unsigned be[2] = { r0, r1 };
                unsigned bo[2] = { r2, r3 };
                mma_f16(acc[0][2*p],     af[0], be);
                mma_f16(acc[0][2*p + 1], af[0], bo);
                mma_f16(acc[1][2*p],     af[1], be);
                mma_f16(acc[1][2*p + 1], af[1], bo);
            }
        }
        __syncthreads();
    }
#undef PREFETCH

#pragma unroll
    for (int mt = 0; mt < 2; mt++) {
        int row = bm + m0 + mt * 16 + g;
#pragma unroll
        for (int nt = 0; nt < 8; nt++) {
            int col = bn + n0 + nt * 8 + 2 * tig;
            float c0 = bias[col], c1 = bias[col + 1];
            store2(C, (size_t)row * 512 + col, acc[mt][nt][0] + c0, acc[mt][nt][1] + c1);
            store2(C, (size_t)(row + 8) * 512 + col, acc[mt][nt][2] + c0, acc[mt][nt][3] + c1);
        }
    }
}

// ---------------- local-window softmax weights (q & k in one launch) --------------
__global__ void k_weights2(const __half* __restrict__ yq, const __half* __restrict__ yk,
                           float* __restrict__ wq, float* __restrict__ wk) {
    const __half* y = blockIdx.y ? yk : yq;
    float* w        = blockIdx.y ? wk : wq;
    int gw = blockIdx.x * 4 + (threadIdx.x >> 5);   // warp -> (n,s)
    int lane = threadIdx.x & 31;
    int n = gw >> 7;
    int s = gw & 127;
    const __half2* base = (const __half2*)(y + (size_t)n * SC * DD);
    const __half2* cen  = base + (size_t)(s + LL - 1) * 256;
    float d0=0.f,d1=0.f,d2=0.f,d3=0.f,d4=0.f;
    for (int i = lane; i < 256; i += 32) {
        float2 cv = __half22float2(cen[i]);
        float2 v0 = __half22float2(base[(s+0)*256 + i]);
        float2 v1 = __half22float2(base[(s+1)*256 + i]);
        float2 v2 = __half22float2(base[(s+2)*256 + i]);
        float2 v3 = __half22float2(base[(s+3)*256 + i]);
        float2 v4 = __half22float2(base[(s+4)*256 + i]);
        d0 += cv.x*v0.x + cv.y*v0.y;
        d1 += cv.x*v1.x + cv.y*v1.y;
        d2 += cv.x*v2.x + cv.y*v2.y;
        d3 += cv.x*v3.x + cv.y*v3.y;
        d4 += cv.x*v4.x + cv.y*v4.y;
    }
#pragma unroll
    for (int off = 16; off; off >>= 1) {
        d0 += __shfl_xor_sync(0xffffffffu, d0, off);
        d1 += __shfl_xor_sync(0xffffffffu, d1, off);
        d2 += __shfl_xor_sync(0xffffffffu, d2, off);
        d3 += __shfl_xor_sync(0xffffffffu, d3, off);
        d4 += __shfl_xor_sync(0xffffffffu, d4, off);
    }
    if (lane == 0) {
        const float sc = 0.044194173824159216f;  // 1/sqrt(512)
        float s0 = d0*sc, s1 = d1*sc, s2 = d2*sc, s3 = d3*sc, s4 = d4*sc;
        float m = fmaxf(fmaxf(fmaxf(s0,s1), fmaxf(s2,s3)), s4);
        float e0 = __expf(s0-m), e1 = __expf(s1-m), e2 = __expf(s2-m),
              e3 = __expf(s3-m), e4 = __expf(s4-m);
        float inv = 1.f / (e0+e1+e2+e3+e4);
        float* wp = w + (size_t)gw * LL;
        wp[0]=e0*inv; wp[1]=e1*inv; wp[2]=e2*inv; wp[3]=e3*inv; wp[4]=e4*inv;
    }
}

// ---------------- scrambled-reshape gather (q & k in one launch) ------------------
__global__ void k_gather2(const __half* __restrict__ yq, const __half* __restrict__ yk,
                          const float* __restrict__ wq, const float* __restrict__ wk,
                          __half* __restrict__ oq, __half* __restrict__ ok) {
    const __half* y = blockIdx.y ? yk : yq;
    const float* w  = blockIdx.y ? wk : wq;
    __half* out     = blockIdx.y ? ok : oq;
    int ns = blockIdx.x;           // n*128 + s
    int n = ns >> 7;
    int s = ns & 127;
    float coef[LL];
    int   rowi[LL];
#pragma unroll
    for (int l = 0; l < LL; l++) {
        int f  = l * SS + s;
        int sp = f / 5;
        int lp = f - sp * 5;
        coef[l] = w[((size_t)n * SS + sp) * LL + lp];
        rowi[l] = sp + lp;
    }
    const uint2* yb = (const uint2*)y + (size_t)n * SC * 128;  // 128 uint2 per row
    int c = threadIdx.x;   // 0..127 (4 halfs each)
    float4 acc = make_float4(0.f,0.f,0.f,0.f);
#pragma unroll
    for (int l = 0; l < LL; l++) {
        uint2 u = yb[(size_t)rowi[l] * 128 + c];
        float2 f0 = __half22float2(*(__half2*)&u.x);
        float2 f1 = __half22float2(*(__half2*)&u.y);
        acc.x += coef[l]*f0.x; acc.y += coef[l]*f0.y;
        acc.z += coef[l]*f1.x; acc.w += coef[l]*f1.y;
    }
    ((uint2*)out)[(size_t)ns * 128 + c] =
        make_uint2(pack_h2(acc.x, acc.y), pack_h2(acc.z, acc.w));
}

// ---------------- attention 1 via fp16 MMA: per (n,h) block, S=128, dk=64 --------
#define A1_QS 36    // word stride Q/K rows (72 halfs)
#define A1_PS 68    // word stride P rows (136 halfs)
#define A1_VS 68    // word stride Vt rows (136 halfs)
__global__ void __launch_bounds__(256) attn1_h(const __half* __restrict__ q,
                                               const __half* __restrict__ k,
                                               const __half* __restrict__ v,
                                               __half* __restrict__ o) {
    extern __shared__ __half hs[];
    __half* Qh = hs;
    __half* Kh = hs + 9216;
    __half* Vt = hs + 18432;
    unsigned* Qw = (unsigned*)Qh;
    unsigned* Kw = (unsigned*)Kh;
    unsigned* Pw = (unsigned*)hs;      // overlay after QK phase
    unsigned* Vw = (unsigned*)Vt;

    int n = blockIdx.x >> 3, h = blockIdx.x & 7;
    int tid = threadIdx.x;
    int lane = tid & 31;
    int g = lane >> 2, tig = lane & 3;
    int m0 = (tid >> 5) * 16;          // warp -> 16 rows

    // stage Q,K: raw fp16 copies (8 halfs/thread/iter)
#pragma unroll
    for (int i = 0; i < 4; i++) {
        int idx = tid + 256 * i;       // 0..1023 = 128 s x 8 dq
        int s = idx >> 3, dq = idx & 7;
        size_t goff = ((size_t)(n * 128 + s)) * 512 + h * 64 + dq * 8;
        *(uint4*)&Qh[s * 72 + dq * 8] = *(const uint4*)(q + goff);
        *(uint4*)&Kh[s * 72 + dq * 8] = *(const uint4*)(k + goff);
    }
    // stage V transposed [d][s] (4 halfs/thread/iter)
#pragma unroll
    for (int i = 0; i < 8; i++) {
        int idx = tid + 256 * i;       // 0..2047 = 128 s x 16 dq
        int s = idx >> 4, dq = idx & 15;
        size_t goff = ((size_t)(n * 128 + s)) * 512 + h * 64 + dq * 4;
        uint2 u = *(const uint2*)(v + goff);
        __half t[4];
        *(uint2*)t = u;
        int d0 = dq * 4;
        Vt[(d0+0) * 136 + s] = t[0];
        Vt[(d0+1) * 136 + s] = t[1];
        Vt[(d0+2) * 136 + s] = t[2];
        Vt[(d0+3) * 136 + s] = t[3];
    }
    __syncthreads();

    float acc[16][4];
#pragma unroll
    for (int nt = 0; nt < 16; nt++)
#pragma unroll
        for (int i = 0; i < 4; i++) acc[nt][i] = 0.f;

#pragma unroll
    for (int kc = 0; kc < 4; kc++) {   // K=64 -> 4 x k16
        int kb2 = kc * 8;
        unsigned af[4];
        af[0] = Qw[(m0 + g) * A1_QS + kb2 + tig];
        af[1] = Qw[(m0 + 8 + g) * A1_QS + kb2 + tig];
        af[2] = Qw[(m0 + g) * A1_QS + kb2 + tig + 4];
        af[3] = Qw[(m0 + 8 + g) * A1_QS + kb2 + tig + 4];
#pragma unroll
        for (int nt = 0; nt < 16; nt++) {
            unsigned bf[2];
            bf[0] = Kw[(nt * 8 + g) * A1_QS + kb2 + tig];
            bf[1] = Kw[(nt * 8 + g) * A1_QS + kb2 + tig + 4];
            mma_f16(acc[nt], af, bf);
        }
    }
    __syncthreads();   // Q/K dead in all warps -> safe to overlay P

    float mx0 = -1e30f, mx1 = -1e30f;
#pragma unroll
    for (int nt = 0; nt < 16; nt++) {
        mx0 = fmaxf(mx0, fmaxf(acc[nt][0], acc[nt][1]));
        mx1 = fmaxf(mx1, fmaxf(acc[nt][2], acc[nt][3]));
    }
    mx0 = fmaxf(mx0, __shfl_xor_sync(0xffffffffu, mx0, 1));
    mx0 = fmaxf(mx0, __shfl_xor_sync(0xffffffffu, mx0, 2));
    mx1 = fmaxf(mx1, __shfl_xor_sync(0xffffffffu, mx1, 1));
    mx1 = fmaxf(mx1, __shfl_xor_sync(0xffffffffu, mx1, 2));
    float sum0 = 0.f, sum1 = 0.f;
#pragma unroll
    for (int nt = 0; nt < 16; nt++) {
        float e0 = __expf(0.125f * (acc[nt][0] - mx0));
        float e1 = __expf(0.125f * (acc[nt][1] - mx0));
        float e2 = __expf(0.125f * (acc[nt][2] - mx1));
        float e3 = __expf(0.125f * (acc[nt][3] - mx1));
        sum0 += e0 + e1;
        sum1 += e2 + e3;
        int cw = nt * 4 + tig;         // word col = (nt*8 + 2tig)/2
        Pw[(m0 + g) * A1_PS + cw]     = pack_h2(e0, e1);
        Pw[(m0 + 8 + g) * A1_PS + cw] = pack_h2(e2, e3);
    }
    sum0 += __shfl_xor_sync(0xffffffffu, sum0, 1);
    sum0 += __shfl_xor_sync(0xffffffffu, sum0, 2);
    sum1 += __shfl_xor_sync(0xffffffffu, sum1, 1);
    sum1 += __shfl_xor_sync(0xffffffffu, sum1, 2);
    float inv0 = 1.f / sum0, inv1 = 1.f / sum1;
    __syncwarp();   // own-warp P rows complete (A-frags read own rows only)

    float oacc[8][4];
#pragma unroll
    for (int nt = 0; nt < 8; nt++)
#pragma unroll
        for (int i = 0; i < 4; i++) oacc[nt][i] = 0.f;

#pragma unroll
    for (int kc = 0; kc < 8; kc++) {
        int kb2 = kc * 8;
        unsigned af[4];
        af[0] = Pw[(m0 + g) * A1_PS + kb2 + tig];
        af[1] = Pw[(m0 + 8 + g) * A1_PS + kb2 + tig];
        af[2] = Pw[(m0 + g) * A1_PS + kb2 + tig + 4];
        af[3] = Pw[(m0 + 8 + g) * A1_PS + kb2 + tig + 4];
#pragma unroll
        for (int nt = 0; nt < 8; nt++) {
            unsigned bf[2];
            bf[0] = Vw[(nt * 8 + g) * A1_VS + kb2 + tig];
            bf[1] = Vw[(nt * 8 + g) * A1_VS + kb2 + tig + 4];
            mma_f16(oacc[nt], af, bf);
        }
    }

    int a = n >> 4, b = n & 15;
    int s0 = m0 + g, s1 = m0 + 8 + g;
    size_t r0 = ((size_t)(s0 * 256 + b * 16 + a)) * 512 + h * 64;
    size_t r1 = ((size_t)(s1 * 256 + b * 16 + a)) * 512 + h * 64;
#pragma unroll
    for (int nt = 0; nt < 8; nt++) {
        int col = nt * 8 + 2 * tig;
        *(unsigned*)&o[r0 + col] = pack_h2(oacc[nt][0] * inv0, oacc[nt][1] * inv0);
        *(unsigned*)&o[r1 + col] = pack_h2(oacc[nt][2] * inv1, oacc[nt][3] * inv1);
    }
}

// ---------------- attention 2 via tf32 MMA: block per sb, 4 warps x 2 heads ------
#define H_STR 516
#define PW_STR 20
__global__ void __launch_bounds__(128) attn2_tc(const __half* __restrict__ xa,
                                                __half* __restrict__ o) {
    __shared__ unsigned hsu[16 * H_STR];
    __shared__ unsigned Pw2[4][16 * PW_STR];
    int sb = blockIdx.x;                      // s*16 + b
    int s_idx = sb >> 4, b_idx = sb & 15;
    int tid = threadIdx.x;
    int wid = tid >> 5, lane = tid & 31;
    int g = lane >> 2, tig = lane & 3;

    const uint4* src = (const uint4*)(xa + (size_t)sb * 16 * DD);  // 8 halfs each
#pragma unroll
    for (int i = 0; i < 8; i++) {
        int it = tid + 128 * i;               // 0..1023
        int r = it >> 6, c = it & 63;
        uint4 u = src[it];
        __half t[8];
        *(uint4*)t = u;
        uint4 w0 = make_uint4(f2tf32(__half2float(t[0])), f2tf32(__half2float(t[1])),
                              f2tf32(__half2float(t[2])), f2tf32(__half2float(t[3])));
        uint4 w1 = make_uint4(f2tf32(__half2float(t[4])), f2tf32(__half2float(t[5])),
                              f2tf32(__half2float(t[6])), f2tf32(__half2float(t[7])));
        *(uint4*)&hsu[r * H_STR + c * 8]     = w0;
        *(uint4*)&hsu[r * H_STR + c * 8 + 4] = w1;
    }
    __syncthreads();

    unsigned* ps = &Pw2[wid][0];
#pragma unroll
    for (int hh = 0; hh < 2; hh++) {
        int base = (wid * 2 + hh) * 64;

        float c[2][4];
#pragma unroll
        for (int nt = 0; nt < 2; nt++)
#pragma unroll
            for (int i = 0; i < 4; i++) c[nt][i] = 0.f;
#pragma unroll
        for (int kc = 0; kc < 8; kc++) {
            int kb = kc * 8;
            unsigned af[4];
            af[0] = hsu[g * H_STR + base + kb + tig];
            af[1] = hsu[(g + 8) * H_STR + base + kb + tig];
            af[2] = hsu[g * H_STR + base + kb + tig + 4];
            af[3] = hsu[(g + 8) * H_STR + base + kb + tig + 4];
#pragma unroll
            for (int nt = 0; nt < 2; nt++) {
                unsigned bf[2];
                bf[0] = hsu[(nt * 8 + g) * H_STR + base + kb + tig];
                bf[1] = hsu[(nt * 8 + g) * H_STR + base + kb + tig + 4];
                mma_tf32(c[nt], af, bf);
            }
        }

        float m0 = fmaxf(fmaxf(c[0][0], c[0][1]), fmaxf(c[1][0], c[1][1]));
        float m1 = fmaxf(fmaxf(c[0][2], c[0][3]), fmaxf(c[1][2], c[1][3]));
        m0 = fmaxf(m0, __shfl_xor_sync(0xffffffffu, m0, 1));
        m0 = fmaxf(m0, __shfl_xor_sync(0xffffffffu, m0, 2));
        m1 = fmaxf(m1, __shfl_xor_sync(0xffffffffu, m1, 1));
        m1 = fmaxf(m1, __shfl_xor_sync(0xffffffffu, m1, 2));
        float m0s = m0 * 0.125f, m1s = m1 * 0.125f;
        float e[2][4];
#pragma unroll
        for (int nt = 0; nt < 2; nt++) {
            e[nt][0] = __expf(c[nt][0] * 0.125f - m0s);
            e[nt][1] = __expf(c[nt][1] * 0.125f - m0s);
            e[nt][2] = __expf(c[nt][2] * 0.125f - m1s);
            e[nt][3] = __expf(c[nt][3] * 0.125f - m1s);
        }
        float s0 = e[0][0] + e[0][1] + e[1][0] + e[1][1];
        float s1 = e[0][2] + e[0][3] + e[1][2] + e[1][3];
        s0 += __shfl_xor_sync(0xffffffffu, s0, 1);
        s0 += __shfl_xor_sync(0xffffffffu, s0, 2);
        s1 += __shfl_xor_sync(0xffffffffu, s1, 1);
        s1 += __shfl_xor_sync(0xffffffffu, s1, 2);
        float inv0 = 1.f / s0, inv1 = 1.f / s1;

#pragma unroll
        for (int nt = 0; nt < 2; nt++) {
            int col = nt * 8 + 2 * tig;
            *(uint2*)&ps[g * PW_STR + col] =
                make_uint2(f2tf32(e[nt][0]), f2tf32(e[nt][1]));
            *(uint2*)&ps[(g + 8) * PW_STR + col] =
                make_uint2(f2tf32(e[nt][2]), f2tf32(e[nt][3]));
        }
        __syncwarp();

        float oc[8][4];
#pragma unroll
        for (int nt = 0; nt < 8; nt++)
#pragma unroll
            for (int i = 0; i < 4; i++) oc[nt][i] = 0.f;
#pragma unroll
        for (int kc = 0; kc < 2; kc++) {
            int kb = kc * 8;
            unsigned af[4];
            af[0] = ps[g * PW_STR + kb + tig];
            af[1] = ps[(g + 8) * PW_STR + kb + tig];
            af[2] = ps[g * PW_STR + kb + tig + 4];
            af[3] = ps[(g + 8) * PW_STR + kb + tig + 4];
#pragma unroll
            for (int nt = 0; nt < 8; nt++) {
                unsigned bf[2];
                bf[0] = hsu[(kb + tig) * H_STR + base + nt * 8 + g];
                bf[1] = hsu[(kb + tig + 4) * H_STR + base + nt * 8 + g];
                mma_tf32(oc[nt], af, bf);
            }
        }

        size_t r0 = ((size_t)((g * 16 + b_idx) * 128 + s_idx)) * 512 + base;
        size_t r1 = ((size_t)(((g + 8) * 16 + b_idx) * 128 + s_idx)) * 512 + base;
#pragma unroll
        for (int nt = 0; nt < 8; nt++) {
            int col = nt * 8 + 2 * tig;
            *(unsigned*)&o[r0 + col] = pack_h2(oc[nt][0] * inv0, oc[nt][1] * inv0);
            *(unsigned*)&o[r1 + col] = pack_h2(oc[nt][2] * inv1, oc[nt][3] * inv1);
        }
        __syncwarp();
    }
}

// =================================================================================
extern "C" void kernel_launch(void* const* d_in, const int* in_sizes, int n_in,
                              void* d_out, int out_size) {
    const float* query = (const float*)d_in[0];
    const float* key   = (const float*)d_in[1];
    const float* value = (const float*)d_in[2];
    // d_in[3] = mask (unused by reference)
    const float* padq  = (const float*)d_in[4];
    const float* padk  = (const float*)d_in[5];
    const float* Wq    = (const float*)d_in[6];
    const float* bq    = (const float*)d_in[7];
    const float* Wk    = (const float*)d_in[8];
    const float* bk    = (const float*)d_in[9];
    const float* Wv    = (const float*)d_in[10];
    const float* bv    = (const float*)d_in[11];
    const float* Wo    = (const float*)d_in[12];
    const float* bo    = (const float*)d_in[13];
    float* out = (float*)d_out;

    __half *xcq, *xck, *yqh, *ykh, *qh, *kh, *vh, *vh2, *xah, *xf, *Wh;
    float *wq, *wk;
    cudaGetSymbolAddress((void**)&xcq, g_xcq);
    cudaGetSymbolAddress((void**)&xck, g_xck);
    cudaGetSymbolAddress((void**)&yqh, g_yqh);
    cudaGetSymbolAddress((void**)&ykh, g_ykh);
    cudaGetSymbolAddress((void**)&wq,  g_wq);
    cudaGetSymbolAddress((void**)&wk,  g_wk);
    cudaGetSymbolAddress((void**)&qh,  g_qh);
    cudaGetSymbolAddress((void**)&kh,  g_kh);
    cudaGetSymbolAddress((void**)&vh,  g_vh);
    cudaGetSymbolAddress((void**)&vh2, g_vh2);
    cudaGetSymbolAddress((void**)&xah, g_xah);
    cudaGetSymbolAddress((void**)&xf,  g_xf);
    cudaGetSymbolAddress((void**)&Wh,  g_Wh);

    const size_t WSZ = (size_t)DD * DD;

    // --- input conversions (fp16), batched ---
    dim3 gconc((NN*SC*128) / 256, 2);            // (16896, 2)
    k_concat_cvt2<<<gconc, 256>>>(query, padq, key, padk, xcq, xck);
    k_cvt_w4<<<1024, 256>>>(Wq, Wk, Wv, Wo, Wh);
    k_cvt_h<<<(NN*SS*DD/4 + 255)/256, 256>>>(value, vh, NN*SS*DD/4);

    // --- projections (fp16 tensor-core + ldmatrix; Q & K batched) ---
    const int gemm_smem = 2 * 2 * GSTG * 4;      // 73728 B
    cudaFuncSetAttribute(gemm_h2<__half>, cudaFuncAttributeMaxDynamicSharedMemorySize, gemm_smem);
    cudaFuncSetAttribute(gemm_h2<float>,  cudaFuncAttributeMaxDynamicSharedMemorySize, gemm_smem);
    dim3 gqk(DD/128, (NN*SC)/128, 2);            // (4, 264, 2)
    gemm_h2<__half><<<gqk, 256, gemm_smem>>>(xcq, Wh + 0*WSZ, bq, yqh,
                                             xck, Wh + 1*WSZ, bk, ykh);
    dim3 gv(DD/128, (NN*SS)/128, 1);             // (4, 256, 1)
    gemm_h2<__half><<<gv, 256, gemm_smem>>>(vh, Wh + 2*WSZ, bv, vh2,
                                            vh, Wh + 2*WSZ, bv, vh2);

    // --- local window reweighting (q & k batched) ---
    dim3 gwt((NN*SS)/4, 2);
    k_weights2<<<gwt, 128>>>(yqh, ykh, wq, wk);
    dim3 ggt(NN*SS, 2);
    k_gather2<<<ggt, 128>>>(yqh, ykh, wq, wk, qh, kh);

    // --- attention 1 (fp16 MMA; fp16 in/out; writes [S,B,A,D]) ---
    const int attn1_smem = 27136 * 2;            // 54272 B
    cudaFuncSetAttribute(attn1_h, cudaFuncAttributeMaxDynamicSharedMemorySize, attn1_smem);
    attn1_h<<<NN*HH, 256, attn1_smem>>>(qh, kh, vh2, xah);

    // --- attention 2 (tf32 core; fp16 in/out; writes [A,B,S,D]) ---
    attn2_tc<<<SS*BB, 128>>>(xah, xf);

    // --- output projection (fp32 out) ---
    gemm_h2<float><<<gv, 256, gemm_smem>>>(xf, Wh + 3*WSZ, bo, out,
                                           xf, Wh + 3*WSZ, bo, out);
}